// round 13
// baseline (speedup 1.0000x reference)
#include <cuda_runtime.h>
#include <cuda_fp16.h>
#include <cstdint>
#include <cstddef>

#define DEVI __device__ __forceinline__

// ---------------- problem sizes ----------------
static constexpr int kM   = 16384;   // 64*256 tokens
static constexpr int kNIn = 512;
static constexpr int kNH  = 1024;
static constexpr int kK   = 1536;    // 512 + 1024
static constexpr int kN   = 4096;    // 4 gates * 1024, gate-interleaved rows (4*j+g)

// ---------------- gemm tiling ----------------
static constexpr int BM = 128;
static constexpr int BN = 128;
static constexpr int BK = 32;                    // halves per k-tile (2 ks-steps of 16)
static constexpr int STAGES = 4;
static constexpr int KITERS = kK / BK;           // 48
static constexpr int CHUNK = 4;                  // k-tiles per fp16->fp32 promotion (K=128)
static constexpr int ROW_B  = 80;                // padded row stride (64B data + 16B pad)
static constexpr int A_BYTES = BM * ROW_B;       // 10240
static constexpr int B_BYTES = BN * ROW_B;       // 10240
static constexpr int STAGE_B = A_BYTES + B_BYTES;            // 20480
static constexpr int SMEM_DYN = STAGES * STAGE_B;            // 81920 (x2 CTA = 160KB/SM)

// ---------------- scratch (device globals; no runtime alloc) ----------------
__device__ __align__(128) __half g_Apack[(size_t)kM * kK];   // 48 MB: [m, 0:512]=x, [m,512:1536]=h
__device__ __align__(128) __half g_Wpack[(size_t)kN * kK];   // 12 MB: row 4j+g
__device__ __align__(16)  float  g_bias[kN];                 // bx+bh, gate-interleaved

// ================= pack kernels =================
struct WPtrs {
    const float* wx[4];
    const float* wh[4];
    const float* bx[4];
    const float* bh[4];
};

DEVI uint4 cvt8(const float* src) {
    float4 a = *(const float4*)src;
    float4 b = *(const float4*)(src + 4);
    __half2 p0 = __floats2half2_rn(a.x, a.y);
    __half2 p1 = __floats2half2_rn(a.z, a.w);
    __half2 p2 = __floats2half2_rn(b.x, b.y);
    __half2 p3 = __floats2half2_rn(b.z, b.w);
    uint4 o;
    o.x = *(const unsigned*)&p0; o.y = *(const unsigned*)&p1;
    o.z = *(const unsigned*)&p2; o.w = *(const unsigned*)&p3;
    return o;
}

__global__ void pack_A_kernel(const float* __restrict__ x, const float* __restrict__ h) {
    unsigned g = blockIdx.x * blockDim.x + threadIdx.x;     // one group of 8 halves
    unsigned m  = g / (kK / 8);
    unsigned kk = (g % (kK / 8)) * 8;
    const float* src = (kk < (unsigned)kNIn) ? (x + (size_t)m * kNIn + kk)
                                             : (h + (size_t)m * kNH + (kk - kNIn));
    *(uint4*)(g_Apack + (size_t)g * 8) = cvt8(src);
}

__global__ void pack_W_kernel(WPtrs p) {
    unsigned g = blockIdx.x * blockDim.x + threadIdx.x;
    unsigned n  = g / (kK / 8);
    unsigned kk = (g % (kK / 8)) * 8;
    unsigned j = n >> 2, gate = n & 3;
    const float* src = (kk < (unsigned)kNIn) ? (p.wx[gate] + (size_t)j * kNIn + kk)
                                             : (p.wh[gate] + (size_t)j * kNH + (kk - kNIn));
    *(uint4*)(g_Wpack + (size_t)g * 8) = cvt8(src);
}

__global__ void pack_bias_kernel(WPtrs p) {
    unsigned n = blockIdx.x * blockDim.x + threadIdx.x;
    if (n < (unsigned)kN) {
        unsigned j = n >> 2, gate = n & 3;
        g_bias[n] = p.bx[gate][j] + p.bh[gate][j];
    }
}

// ================= ptx helpers (sm_100-base-target safe) =================
DEVI uint32_t smem_u32(const void* p) {
    uint32_t a;
    asm("{ .reg .u64 t; cvta.to.shared.u64 t, %1; cvt.u32.u64 %0, t; }" : "=r"(a) : "l"(p));
    return a;
}
DEVI void cp_async16(uint32_t saddr, const void* gaddr) {
    asm volatile("cp.async.cg.shared.global [%0], [%1], 16;" :: "r"(saddr), "l"(gaddr));
}
DEVI void cp_commit() { asm volatile("cp.async.commit_group;" ::: "memory"); }
template <int N> DEVI void cp_wait() { asm volatile("cp.async.wait_group %0;" :: "n"(N) : "memory"); }

DEVI void ldsm_x4(uint32_t& r0, uint32_t& r1, uint32_t& r2, uint32_t& r3, uint32_t addr) {
    asm volatile("ldmatrix.sync.aligned.m8n8.x4.shared.b16 {%0,%1,%2,%3}, [%4];"
                 : "=r"(r0), "=r"(r1), "=r"(r2), "=r"(r3) : "r"(addr));
}
// fp16-accumulator MMA: D,C are 2 b32 regs (4 halves). Full-rate tensor path.
DEVI void mma16816_f16(uint32_t* d, const uint32_t* a, uint32_t b0, uint32_t b1) {
    asm volatile(
        "mma.sync.aligned.m16n8k16.row.col.f16.f16.f16.f16 "
        "{%0,%1}, {%2,%3,%4,%5}, {%6,%7}, {%0,%1};"
        : "+r"(d[0]), "+r"(d[1])
        : "r"(a[0]), "r"(a[1]), "r"(a[2]), "r"(a[3]), "r"(b0), "r"(b1));
}

DEVI float tanha(float x) { float y; asm("tanh.approx.f32 %0, %1;" : "=f"(y) : "f"(x)); return y; }
DEVI float sigf(float x)  { return fmaf(0.5f, tanha(0.5f * x), 0.5f); }

// ================= fused GEMM + LSTM epilogue =================
// CTA 128x128, 256 threads = 8 warps, warp grid 4(M) x 2(N); warp tile 32x64.
// 2 CTAs/SM. fp16 accumulators (full-rate HMMA) over CHUNK=4 k-tiles (K=128,
// small running sums -> small ulp), promoted into fp32 accumulators per chunk.
__global__ void __launch_bounds__(256, 2) lstm_gemm_kernel(
    const float* __restrict__ c_in,
    float* __restrict__ outC,
    float* __restrict__ outH)
{
    extern __shared__ char smem[];
    const uint32_t sb = smem_u32(smem);

    const int tid  = threadIdx.x;
    const int lane = tid & 31;
    const int wid  = tid >> 5;
    const int wm   = (wid & 3) * 32;     // warp M offset in tile
    const int wn   = (wid >> 2) * 64;    // warp N offset in tile
    const int m0   = blockIdx.x * BM;
    const int n0   = blockIdx.y * BN;

    // --- cp.async stage loader: 4 x 16B per thread per stage ---
    auto load_stage = [&](int stage, int kt) {
        const uint32_t sA = sb + stage * STAGE_B;
        const uint32_t sB = sA + A_BYTES;
        const int kh = kt * BK;                       // k offset in halves
#pragma unroll
        for (int i = 0; i < 2; i++) {
            int id  = tid + i * 256;                  // 0..511
            int row = id >> 2;
            int seg = id & 3;
            cp_async16(sA + row * ROW_B + seg * 16,
                       g_Apack + (size_t)(m0 + row) * kK + kh + seg * 8);
            cp_async16(sB + row * ROW_B + seg * 16,
                       g_Wpack + (size_t)(n0 + row) * kK + kh + seg * 8);
        }
    };

    // prologue: stages 0..STAGES-2
#pragma unroll
    for (int s = 0; s < STAGES - 1; s++) { load_stage(s, s); cp_commit(); }

    float acc_f[2][8][4];                             // promoted fp32 accumulators
    uint32_t acc_h[2][8][2];                          // fp16 chunk accumulators (half2 pairs)
#pragma unroll
    for (int mf = 0; mf < 2; mf++)
#pragma unroll
        for (int nf = 0; nf < 8; nf++) {
#pragma unroll
            for (int r = 0; r < 4; r++) acc_f[mf][nf][r] = 0.0f;
            acc_h[mf][nf][0] = 0u; acc_h[mf][nf][1] = 0u;
        }

    // per-lane ldmatrix address components
    const int a_row = wm + (lane & 15);               // + mf*16
    const int a_kof = (lane >> 4) << 3;               // + ks
    const int b_row = wn + (lane & 7) + ((lane >> 4) << 3);   // + nb*16
    const int b_kof = ((lane >> 3) & 1) << 3;         // + ks

    for (int kt = 0; kt < KITERS; kt++) {
        cp_wait<STAGES - 2>();
        __syncthreads();
        int pf = kt + STAGES - 1;
        if (pf < KITERS) load_stage(pf & (STAGES - 1), pf);
        cp_commit();

        const int st = kt & (STAGES - 1);
        const uint32_t sA = sb + st * STAGE_B;
        const uint32_t sB = sA + A_BYTES;

#pragma unroll
        for (int ks = 0; ks < BK; ks += 16) {
            uint32_t ra[2][4], rb[4][4];
#pragma unroll
            for (int mf = 0; mf < 2; mf++)
                ldsm_x4(ra[mf][0], ra[mf][1], ra[mf][2], ra[mf][3],
                        sA + (a_row + mf * 16) * ROW_B + (ks + a_kof) * 2);
#pragma unroll
            for (int nb = 0; nb < 4; nb++)
                ldsm_x4(rb[nb][0], rb[nb][1], rb[nb][2], rb[nb][3],
                        sB + (b_row + nb * 16) * ROW_B + (ks + b_kof) * 2);
#pragma unroll
            for (int mf = 0; mf < 2; mf++)
#pragma unroll
                for (int nf = 0; nf < 8; nf++)
                    mma16816_f16(acc_h[mf][nf], ra[mf],
                                 rb[nf >> 1][(nf & 1) * 2], rb[nf >> 1][(nf & 1) * 2 + 1]);
        }

        // end of chunk: promote fp16 partial sums into fp32, reset fp16 accs
        if ((kt & (CHUNK - 1)) == (CHUNK - 1)) {
#pragma unroll
            for (int mf = 0; mf < 2; mf++)
#pragma unroll
                for (int nf = 0; nf < 8; nf++) {
                    float2 f0 = __half22float2(*(__half2*)&acc_h[mf][nf][0]);
                    float2 f1 = __half22float2(*(__half2*)&acc_h[mf][nf][1]);
                    acc_f[mf][nf][0] += f0.x;
                    acc_f[mf][nf][1] += f0.y;
                    acc_f[mf][nf][2] += f1.x;
                    acc_f[mf][nf][3] += f1.y;
                    acc_h[mf][nf][0] = 0u;
                    acc_h[mf][nf][1] = 0u;
                }
        }
    }

    // ---------- fused LSTM epilogue (from fp32 accumulators) ----------
    // fp16-acc frag layout matches fp32 path: d0,d1 -> (row=g, cols 2*tig+{0,1});
    // d2,d3 -> (row=g+8). Gate-interleaved N: cols 4u..4u+3 = i,f,g,o of unit u.
    // Even tig holds (zi,zf); odd tig holds (zg,zo). Pair-exchange via shfl.xor(1):
    //   even thread -> full quadruple for row g;  odd thread -> row g+8.
    const int g8   = lane >> 2;
    const int tig  = lane & 3;
    const bool odd = tig & 1;
    const int jsub = tig >> 1;                        // unit-within-nfrag

#pragma unroll
    for (int mf = 0; mf < 2; mf++) {
        const int m = m0 + wm + mf * 16 + g8 + (odd ? 8 : 0);
        const float* crow = c_in + (size_t)m * kNH;
        float* ocrow = outC + (size_t)m * kNH;
        float* ohrow = outH + (size_t)m * kNH;
#pragma unroll
        for (int nf = 0; nf < 8; nf++) {
            float* d = acc_f[mf][nf];
            float v0 = __shfl_xor_sync(0xffffffffu, d[0], 1);
            float v1 = __shfl_xor_sync(0xffffffffu, d[1], 1);
            float v2 = __shfl_xor_sync(0xffffffffu, d[2], 1);
            float v3 = __shfl_xor_sync(0xffffffffu, d[3], 1);
            float zi = odd ? v2 : d[0];
            float zf = odd ? v3 : d[1];
            float zg = odd ? d[2] : v0;
            float zo = odd ? d[3] : v1;
            const int ncol = n0 + wn + nf * 8;        // global gemm column base
            const int j = (ncol >> 2) + jsub;         // hidden-unit index
            float4 bb = __ldg((const float4*)(g_bias + 4 * j));
            zi += bb.x; zf += bb.y; zg += bb.z; zo += bb.w;
            float it = sigf(zi), ft = sigf(zf), gt = tanha(zg), ot = sigf(zo);
            float cc = ft * __ldg(crow + j) + it * gt;
            ocrow[j] = cc;
            ohrow[j] = ot * tanha(cc);
        }
    }
}

// ================= host launch =================
extern "C" void kernel_launch(void* const* d_in, const int* in_sizes, int n_in,
                              void* d_out, int out_size)
{
    const float* x = (const float*)d_in[0];
    const float* c = (const float*)d_in[1];
    const float* h = (const float*)d_in[2];
    WPtrs wp;
    for (int g = 0; g < 4; g++) {
        wp.wx[g] = (const float*)d_in[3 + 2 * g];
        wp.bx[g] = (const float*)d_in[4 + 2 * g];
        wp.wh[g] = (const float*)d_in[11 + 2 * g];
        wp.bh[g] = (const float*)d_in[12 + 2 * g];
    }

    cudaFuncSetAttribute(lstm_gemm_kernel,
                         cudaFuncAttributeMaxDynamicSharedMemorySize, SMEM_DYN);

    pack_A_kernel<<<(kM * (kK / 8)) / 256, 256>>>(x, h);
    pack_W_kernel<<<(kN * (kK / 8)) / 256, 256>>>(wp);
    pack_bias_kernel<<<kN / 256, 256>>>(wp);

    float* outC = (float*)d_out;
    float* outH = outC + (size_t)kM * kNH;
    lstm_gemm_kernel<<<dim3(kM / BM, kN / BN), 256, SMEM_DYN>>>(c, outC, outH);
}

// round 14
// speedup vs baseline: 1.1453x; 1.1453x over previous
#include <cuda_runtime.h>
#include <cuda_fp16.h>
#include <cstdint>
#include <cstddef>

#define DEVI __device__ __forceinline__

// ---------------- problem sizes ----------------
static constexpr int kM   = 16384;   // 64*256 tokens
static constexpr int kNIn = 512;
static constexpr int kNH  = 1024;
static constexpr int kK   = 1536;    // 512 + 1024
static constexpr int kN   = 4096;    // 4 gates * 1024, gate-interleaved rows (4*j+g)

// ---------------- gemm tiling ----------------
static constexpr int BM = 128;
static constexpr int BN = 128;
static constexpr int BK = 32;                    // halves per k-tile (2 ks-steps of 16)
static constexpr int STAGES = 4;
static constexpr int KITERS = kK / BK;           // 48
static constexpr int MTILES = kM / BM;           // 128
static constexpr int NTILES = kN / BN;           // 32
static constexpr int TOTAL_TILES = MTILES * NTILES;          // 4096
static constexpr int ROW_B  = 80;                // padded row stride (64B data + 16B pad)
static constexpr int A_BYTES = BM * ROW_B;       // 10240
static constexpr int B_BYTES = BN * ROW_B;       // 10240
static constexpr int STAGE_B = A_BYTES + B_BYTES;            // 20480
static constexpr int SMEM_DYN = STAGES * STAGE_B;            // 81920 (x2 CTA = 160KB/SM)

// ---------------- scratch (device globals; no runtime alloc) ----------------
__device__ __align__(128) __half g_Apack[(size_t)kM * kK];   // 48 MB: [m, 0:512]=x, [m,512:1536]=h
__device__ __align__(128) __half g_Wpack[(size_t)kN * kK];   // 12 MB: row 4j+g
__device__ __align__(16)  float  g_bias[kN];                 // bx+bh, gate-interleaved

// ================= fused pack kernel =================
struct WPtrs {
    const float* wx[4];
    const float* wh[4];
    const float* bx[4];
    const float* bh[4];
};

DEVI uint4 cvt8(const float* src) {
    float4 a = *(const float4*)src;
    float4 b = *(const float4*)(src + 4);
    __half2 p0 = __floats2half2_rn(a.x, a.y);
    __half2 p1 = __floats2half2_rn(a.z, a.w);
    __half2 p2 = __floats2half2_rn(b.x, b.y);
    __half2 p3 = __floats2half2_rn(b.z, b.w);
    uint4 o;
    o.x = *(const unsigned*)&p0; o.y = *(const unsigned*)&p1;
    o.z = *(const unsigned*)&p2; o.w = *(const unsigned*)&p3;
    return o;
}

static constexpr unsigned A_CHUNKS = (unsigned)kM * (kK / 8);    // 3145728
static constexpr unsigned W_CHUNKS = (unsigned)kN * (kK / 8);    // 786432
static constexpr unsigned PACK_THREADS = A_CHUNKS + W_CHUNKS + kN;

__global__ void pack_all_kernel(const float* __restrict__ x, const float* __restrict__ h,
                                WPtrs p) {
    unsigned id = blockIdx.x * blockDim.x + threadIdx.x;
    if (id < A_CHUNKS) {
        unsigned m  = id / (kK / 8);
        unsigned kk = (id % (kK / 8)) * 8;
        const float* src = (kk < (unsigned)kNIn) ? (x + (size_t)m * kNIn + kk)
                                                 : (h + (size_t)m * kNH + (kk - kNIn));
        *(uint4*)(g_Apack + (size_t)id * 8) = cvt8(src);
    } else if (id < A_CHUNKS + W_CHUNKS) {
        unsigned g  = id - A_CHUNKS;
        unsigned n  = g / (kK / 8);
        unsigned kk = (g % (kK / 8)) * 8;
        unsigned j = n >> 2, gate = n & 3;
        const float* src = (kk < (unsigned)kNIn) ? (p.wx[gate] + (size_t)j * kNIn + kk)
                                                 : (p.wh[gate] + (size_t)j * kNH + (kk - kNIn));
        *(uint4*)(g_Wpack + (size_t)g * 8) = cvt8(src);
    } else if (id < PACK_THREADS) {
        unsigned n = id - A_CHUNKS - W_CHUNKS;
        unsigned j = n >> 2, gate = n & 3;
        g_bias[n] = p.bx[gate][j] + p.bh[gate][j];
    }
}

// ================= ptx helpers (sm_100-base-target safe) =================
DEVI uint32_t smem_u32(const void* p) {
    uint32_t a;
    asm("{ .reg .u64 t; cvta.to.shared.u64 t, %1; cvt.u32.u64 %0, t; }" : "=r"(a) : "l"(p));
    return a;
}
DEVI void cp_async16(uint32_t saddr, const void* gaddr) {
    asm volatile("cp.async.cg.shared.global [%0], [%1], 16;" :: "r"(saddr), "l"(gaddr));
}
DEVI void cp_commit() { asm volatile("cp.async.commit_group;" ::: "memory"); }
template <int N> DEVI void cp_wait() { asm volatile("cp.async.wait_group %0;" :: "n"(N) : "memory"); }

DEVI void ldsm_x4(uint32_t& r0, uint32_t& r1, uint32_t& r2, uint32_t& r3, uint32_t addr) {
    asm volatile("ldmatrix.sync.aligned.m8n8.x4.shared.b16 {%0,%1,%2,%3}, [%4];"
                 : "=r"(r0), "=r"(r1), "=r"(r2), "=r"(r3) : "r"(addr));
}
DEVI void mma16816(float* d, const uint32_t* a, uint32_t b0, uint32_t b1) {
    asm volatile(
        "mma.sync.aligned.m16n8k16.row.col.f32.f16.f16.f32 "
        "{%0,%1,%2,%3}, {%4,%5,%6,%7}, {%8,%9}, {%0,%1,%2,%3};"
        : "+f"(d[0]), "+f"(d[1]), "+f"(d[2]), "+f"(d[3])
        : "r"(a[0]), "r"(a[1]), "r"(a[2]), "r"(a[3]), "r"(b0), "r"(b1));
}

DEVI float tanha(float x) { float y; asm("tanh.approx.f32 %0, %1;" : "=f"(y) : "f"(x)); return y; }
DEVI float sigf(float x)  { return fmaf(0.5f, tanha(0.5f * x), 0.5f); }

// ================= fused GEMM + LSTM epilogue (persistent CTAs) =================
// CTA 128x128, 256 threads = 8 warps, warp grid 4(M) x 2(N); warp tile 32x64.
// 2 CTAs/SM. Persistent CTAs: each processes tiles bid, bid+grid, ... with a
// CONTINUOUS cp.async stage ring across tiles (pipeline never refills) plus the
// R12 cross-tile fragment pipelining within and across tile boundaries.
__global__ void __launch_bounds__(256, 2) lstm_gemm_kernel(
    const float* __restrict__ c_in,
    float* __restrict__ outC,
    float* __restrict__ outH)
{
    extern __shared__ char smem[];
    const uint32_t sb = smem_u32(smem);

    const int tid  = threadIdx.x;
    const int lane = tid & 31;
    const int wid  = tid >> 5;
    const int wm   = (wid & 3) * 32;     // warp M offset in tile
    const int wn   = (wid >> 2) * 64;    // warp N offset in tile
    const int stride = gridDim.x;

    // ---- rolling fill cursor (tile t_load, k-tile kt_load) ----
    int t_load  = blockIdx.x;
    int kt_load = 0;
    int m0l = (t_load & (MTILES - 1)) * BM;
    int n0l = (t_load >> 7) * BN;

    auto do_fill = [&](int stage) {
        if (t_load < TOTAL_TILES) {
            const uint32_t sA = sb + stage * STAGE_B;
            const uint32_t sB = sA + A_BYTES;
            const int kh = kt_load * BK;
#pragma unroll
            for (int i = 0; i < 2; i++) {
                int id  = tid + i * 256;              // 0..511
                int row = id >> 2;
                int seg = id & 3;
                cp_async16(sA + row * ROW_B + seg * 16,
                           g_Apack + (size_t)(m0l + row) * kK + kh + seg * 8);
                cp_async16(sB + row * ROW_B + seg * 16,
                           g_Wpack + (size_t)(n0l + row) * kK + kh + seg * 8);
            }
            if (++kt_load == KITERS) {
                kt_load = 0;
                t_load += stride;
                m0l = (t_load & (MTILES - 1)) * BM;
                n0l = (t_load >> 7) * BN;
            }
        }
        cp_commit();
    };

    // per-lane ldmatrix address components
    const int a_row = wm + (lane & 15);               // + mf*16
    const int a_kof = (lane >> 4) << 3;               // + ks
    const int b_row = wn + (lane & 7) + ((lane >> 4) << 3);   // + nb*16
    const int b_kof = ((lane >> 3) & 1) << 3;         // + ks

    uint32_t ra[2][2][4], rb[2][4][4];                // [buf][frag][reg]

    auto ldsm_step = [&](int buf, int stage, int ks) {
        const uint32_t sA = sb + stage * STAGE_B;
        const uint32_t sB = sA + A_BYTES;
#pragma unroll
        for (int mf = 0; mf < 2; mf++)
            ldsm_x4(ra[buf][mf][0], ra[buf][mf][1], ra[buf][mf][2], ra[buf][mf][3],
                    sA + (a_row + mf * 16) * ROW_B + (ks + a_kof) * 2);
#pragma unroll
        for (int nb = 0; nb < 4; nb++)
            ldsm_x4(rb[buf][nb][0], rb[buf][nb][1], rb[buf][nb][2], rb[buf][nb][3],
                    sB + (b_row + nb * 16) * ROW_B + (ks + b_kof) * 2);
    };

    float acc[2][8][4];
    auto mma_step = [&](int buf) {
#pragma unroll
        for (int mf = 0; mf < 2; mf++)
#pragma unroll
            for (int nf = 0; nf < 8; nf++)
                mma16816(acc[mf][nf], ra[buf][mf],
                         rb[buf][nf >> 1][(nf & 1) * 2], rb[buf][nf >> 1][(nf & 1) * 2 + 1]);
    };

    // epilogue lane constants
    const int g8   = lane >> 2;
    const int tig  = lane & 3;
    const bool odd = tig & 1;
    const int jsub = tig >> 1;

    // ---- prologue: fills 0,1,2 of the continuous ring ----
    do_fill(0); do_fill(1); do_fill(2);
    cp_wait<1>();
    __syncthreads();

    int g = 0;                                        // global consume counter
    ldsm_step(0, 0, 0);                               // (first tile, ks0) -> buf0

    for (int t = blockIdx.x; t < TOTAL_TILES; t += stride) {
        const int m0 = (t & (MTILES - 1)) * BM;
        const int n0 = (t >> 7) * BN;

#pragma unroll
        for (int mf = 0; mf < 2; mf++)
#pragma unroll
            for (int nf = 0; nf < 8; nf++)
#pragma unroll
                for (int r = 0; r < 4; r++) acc[mf][nf][r] = 0.0f;

        for (int kt = 0; kt < KITERS; kt++) {
            const int st = g & 3;
            do_fill((g + 3) & 3);                     // fill index g+3 (ring continues)

            ldsm_step(1, st, 16);                     // (g, ks1) -> buf1
            mma_step(0);                              // MMA (g, ks0)
            if (kt < KITERS - 1)
                ldsm_step(0, (g + 1) & 3, 0);         // (g+1, ks0) -> buf0 (stage visible)
            mma_step(1);                              // MMA (g, ks1)

            // done <= group g+2 -> after barrier, stages g+1 AND g+2 visible to all
            cp_wait<1>();
            __syncthreads();
            g++;
        }

        // ---------- fused LSTM epilogue (from accumulator registers) ----------
        // c-frag layout: d0,d1 -> (row=gr, cols 2*tig+{0,1}); d2,d3 -> (row=gr+8).
        // Gate-interleaved N: cols 4u..4u+3 = gates i,f,g,o of hidden unit.
        // Even tig holds (zi,zf); odd tig holds (zg,zo). Pair-exchange via shfl.xor(1).
#pragma unroll
        for (int mf = 0; mf < 2; mf++) {
            const int m = m0 + wm + mf * 16 + g8 + (odd ? 8 : 0);
            const float* crow = c_in + (size_t)m * kNH;
            float* ocrow = outC + (size_t)m * kNH;
            float* ohrow = outH + (size_t)m * kNH;
#pragma unroll
            for (int nf = 0; nf < 8; nf++) {
                float* d = acc[mf][nf];
                float v0 = __shfl_xor_sync(0xffffffffu, d[0], 1);
                float v1 = __shfl_xor_sync(0xffffffffu, d[1], 1);
                float v2 = __shfl_xor_sync(0xffffffffu, d[2], 1);
                float v3 = __shfl_xor_sync(0xffffffffu, d[3], 1);
                float zi = odd ? v2 : d[0];
                float zf = odd ? v3 : d[1];
                float zg = odd ? d[2] : v0;
                float zo = odd ? d[3] : v1;
                const int ncol = n0 + wn + nf * 8;    // global gemm column base
                const int j = (ncol >> 2) + jsub;     // hidden-unit index
                float4 bb = __ldg((const float4*)(g_bias + 4 * j));
                zi += bb.x; zf += bb.y; zg += bb.z; zo += bb.w;
                float it = sigf(zi), ft = sigf(zf), gt = tanha(zg), ot = sigf(zo);
                float cc = ft * __ldg(crow + j) + it * gt;
                ocrow[j] = cc;
                ohrow[j] = ot * tanha(cc);
            }
        }

        // first fragments of the NEXT tile (stage g visible from the last wait)
        if (t + stride < TOTAL_TILES)
            ldsm_step(0, g & 3, 0);
    }
}

// ================= host launch =================
extern "C" void kernel_launch(void* const* d_in, const int* in_sizes, int n_in,
                              void* d_out, int out_size)
{
    const float* x = (const float*)d_in[0];
    const float* c = (const float*)d_in[1];
    const float* h = (const float*)d_in[2];
    WPtrs wp;
    for (int g = 0; g < 4; g++) {
        wp.wx[g] = (const float*)d_in[3 + 2 * g];
        wp.bx[g] = (const float*)d_in[4 + 2 * g];
        wp.wh[g] = (const float*)d_in[11 + 2 * g];
        wp.bh[g] = (const float*)d_in[12 + 2 * g];
    }

    cudaFuncSetAttribute(lstm_gemm_kernel,
                         cudaFuncAttributeMaxDynamicSharedMemorySize, SMEM_DYN);

    int smCount = 148;
    cudaDeviceGetAttribute(&smCount, cudaDevAttrMultiProcessorCount, 0);
    const int numCtas = 2 * smCount;                  // 2 CTAs/SM persistent

    pack_all_kernel<<<(PACK_THREADS + 255) / 256, 256>>>(x, h, wp);

    float* outC = (float*)d_out;
    float* outH = outC + (size_t)kM * kNH;
    lstm_gemm_kernel<<<numCtas, 256, SMEM_DYN>>>(c, outC, outH);
}

// round 15
// speedup vs baseline: 1.2040x; 1.0513x over previous
#include <cuda_runtime.h>
#include <cuda_fp16.h>
#include <cstdint>
#include <cstddef>

#define DEVI __device__ __forceinline__

// ---------------- problem sizes ----------------
static constexpr int kM   = 16384;   // 64*256 tokens
static constexpr int kNIn = 512;
static constexpr int kNH  = 1024;
static constexpr int kK   = 1536;    // 512 + 1024
static constexpr int kN   = 4096;    // 4 gates * 1024, gate-interleaved rows (4*j+g)

// ---------------- gemm tiling ----------------
static constexpr int BM = 128;
static constexpr int BN = 128;
static constexpr int BK = 32;                    // halves per k-tile (2 ks-steps of 16)
static constexpr int STAGES = 4;
static constexpr int KITERS = kK / BK;           // 48
static constexpr int MTILES = kM / BM;           // 128
static constexpr int NTILES = kN / BN;           // 32
static constexpr int TOTAL_TILES = MTILES * NTILES;          // 4096
static constexpr int ROW_B  = 80;                // padded row stride (64B data + 16B pad)
static constexpr int A_BYTES = BM * ROW_B;       // 10240
static constexpr int B_BYTES = BN * ROW_B;       // 10240
static constexpr int STAGE_B = A_BYTES + B_BYTES;            // 20480
static constexpr int SMEM_DYN = STAGES * STAGE_B;            // 81920 (x2 CTA = 160KB/SM)

// ---------------- scratch (device globals; no runtime alloc) ----------------
__device__ __align__(128) __half g_Apack[(size_t)kM * kK];   // 48 MB: [m, 0:512]=x, [m,512:1536]=h
__device__ __align__(128) __half g_Wpack[(size_t)kN * kK];   // 12 MB: row 4j+g
__device__ __align__(16)  float  g_bias[kN];                 // bx+bh, gate-interleaved

// ================= pack kernels (R12 configuration — 3 separate launches) =================
struct WPtrs {
    const float* wx[4];
    const float* wh[4];
    const float* bx[4];
    const float* bh[4];
};

DEVI uint4 cvt8(const float* src) {
    float4 a = *(const float4*)src;
    float4 b = *(const float4*)(src + 4);
    __half2 p0 = __floats2half2_rn(a.x, a.y);
    __half2 p1 = __floats2half2_rn(a.z, a.w);
    __half2 p2 = __floats2half2_rn(b.x, b.y);
    __half2 p3 = __floats2half2_rn(b.z, b.w);
    uint4 o;
    o.x = *(const unsigned*)&p0; o.y = *(const unsigned*)&p1;
    o.z = *(const unsigned*)&p2; o.w = *(const unsigned*)&p3;
    return o;
}

__global__ void pack_A_kernel(const float* __restrict__ x, const float* __restrict__ h) {
    unsigned g = blockIdx.x * blockDim.x + threadIdx.x;     // one group of 8 halves
    unsigned m  = g / (kK / 8);
    unsigned kk = (g % (kK / 8)) * 8;
    const float* src = (kk < (unsigned)kNIn) ? (x + (size_t)m * kNIn + kk)
                                             : (h + (size_t)m * kNH + (kk - kNIn));
    *(uint4*)(g_Apack + (size_t)g * 8) = cvt8(src);
}

__global__ void pack_W_kernel(WPtrs p) {
    unsigned g = blockIdx.x * blockDim.x + threadIdx.x;
    unsigned n  = g / (kK / 8);
    unsigned kk = (g % (kK / 8)) * 8;
    unsigned j = n >> 2, gate = n & 3;
    const float* src = (kk < (unsigned)kNIn) ? (p.wx[gate] + (size_t)j * kNIn + kk)
                                             : (p.wh[gate] + (size_t)j * kNH + (kk - kNIn));
    *(uint4*)(g_Wpack + (size_t)g * 8) = cvt8(src);
}

__global__ void pack_bias_kernel(WPtrs p) {
    unsigned n = blockIdx.x * blockDim.x + threadIdx.x;
    if (n < (unsigned)kN) {
        unsigned j = n >> 2, gate = n & 3;
        g_bias[n] = p.bx[gate][j] + p.bh[gate][j];
    }
}

// ================= ptx helpers (sm_100-base-target safe) =================
DEVI uint32_t smem_u32(const void* p) {
    uint32_t a;
    asm("{ .reg .u64 t; cvta.to.shared.u64 t, %1; cvt.u32.u64 %0, t; }" : "=r"(a) : "l"(p));
    return a;
}
DEVI void cp_async16(uint32_t saddr, const void* gaddr) {
    asm volatile("cp.async.cg.shared.global [%0], [%1], 16;" :: "r"(saddr), "l"(gaddr));
}
DEVI void cp_commit() { asm volatile("cp.async.commit_group;" ::: "memory"); }
template <int N> DEVI void cp_wait() { asm volatile("cp.async.wait_group %0;" :: "n"(N) : "memory"); }

DEVI void ldsm_x4(uint32_t& r0, uint32_t& r1, uint32_t& r2, uint32_t& r3, uint32_t addr) {
    asm volatile("ldmatrix.sync.aligned.m8n8.x4.shared.b16 {%0,%1,%2,%3}, [%4];"
                 : "=r"(r0), "=r"(r1), "=r"(r2), "=r"(r3) : "r"(addr));
}
DEVI void mma16816(float* d, const uint32_t* a, uint32_t b0, uint32_t b1) {
    asm volatile(
        "mma.sync.aligned.m16n8k16.row.col.f32.f16.f16.f32 "
        "{%0,%1,%2,%3}, {%4,%5,%6,%7}, {%8,%9}, {%0,%1,%2,%3};"
        : "+f"(d[0]), "+f"(d[1]), "+f"(d[2]), "+f"(d[3])
        : "r"(a[0]), "r"(a[1]), "r"(a[2]), "r"(a[3]), "r"(b0), "r"(b1));
}

DEVI float tanha(float x) { float y; asm("tanh.approx.f32 %0, %1;" : "=f"(y) : "f"(x)); return y; }
DEVI float sigf(float x)  { return fmaf(0.5f, tanha(0.5f * x), 0.5f); }

// ================= fused GEMM + LSTM epilogue (persistent CTAs, R14 verbatim) =================
// CTA 128x128, 256 threads = 8 warps, warp grid 4(M) x 2(N); warp tile 32x64.
// 2 CTAs/SM. Persistent CTAs: each processes tiles bid, bid+grid, ... with a
// CONTINUOUS cp.async stage ring across tiles (pipeline never refills) plus the
// R12 cross-tile fragment pipelining within and across tile boundaries.
__global__ void __launch_bounds__(256, 2) lstm_gemm_kernel(
    const float* __restrict__ c_in,
    float* __restrict__ outC,
    float* __restrict__ outH)
{
    extern __shared__ char smem[];
    const uint32_t sb = smem_u32(smem);

    const int tid  = threadIdx.x;
    const int lane = tid & 31;
    const int wid  = tid >> 5;
    const int wm   = (wid & 3) * 32;     // warp M offset in tile
    const int wn   = (wid >> 2) * 64;    // warp N offset in tile
    const int stride = gridDim.x;

    // ---- rolling fill cursor (tile t_load, k-tile kt_load) ----
    int t_load  = blockIdx.x;
    int kt_load = 0;
    int m0l = (t_load & (MTILES - 1)) * BM;
    int n0l = (t_load >> 7) * BN;

    auto do_fill = [&](int stage) {
        if (t_load < TOTAL_TILES) {
            const uint32_t sA = sb + stage * STAGE_B;
            const uint32_t sB = sA + A_BYTES;
            const int kh = kt_load * BK;
#pragma unroll
            for (int i = 0; i < 2; i++) {
                int id  = tid + i * 256;              // 0..511
                int row = id >> 2;
                int seg = id & 3;
                cp_async16(sA + row * ROW_B + seg * 16,
                           g_Apack + (size_t)(m0l + row) * kK + kh + seg * 8);
                cp_async16(sB + row * ROW_B + seg * 16,
                           g_Wpack + (size_t)(n0l + row) * kK + kh + seg * 8);
            }
            if (++kt_load == KITERS) {
                kt_load = 0;
                t_load += stride;
                m0l = (t_load & (MTILES - 1)) * BM;
                n0l = (t_load >> 7) * BN;
            }
        }
        cp_commit();
    };

    // per-lane ldmatrix address components
    const int a_row = wm + (lane & 15);               // + mf*16
    const int a_kof = (lane >> 4) << 3;               // + ks
    const int b_row = wn + (lane & 7) + ((lane >> 4) << 3);   // + nb*16
    const int b_kof = ((lane >> 3) & 1) << 3;         // + ks

    uint32_t ra[2][2][4], rb[2][4][4];                // [buf][frag][reg]

    auto ldsm_step = [&](int buf, int stage, int ks) {
        const uint32_t sA = sb + stage * STAGE_B;
        const uint32_t sB = sA + A_BYTES;
#pragma unroll
        for (int mf = 0; mf < 2; mf++)
            ldsm_x4(ra[buf][mf][0], ra[buf][mf][1], ra[buf][mf][2], ra[buf][mf][3],
                    sA + (a_row + mf * 16) * ROW_B + (ks + a_kof) * 2);
#pragma unroll
        for (int nb = 0; nb < 4; nb++)
            ldsm_x4(rb[buf][nb][0], rb[buf][nb][1], rb[buf][nb][2], rb[buf][nb][3],
                    sB + (b_row + nb * 16) * ROW_B + (ks + b_kof) * 2);
    };

    float acc[2][8][4];
    auto mma_step = [&](int buf) {
#pragma unroll
        for (int mf = 0; mf < 2; mf++)
#pragma unroll
            for (int nf = 0; nf < 8; nf++)
                mma16816(acc[mf][nf], ra[buf][mf],
                         rb[buf][nf >> 1][(nf & 1) * 2], rb[buf][nf >> 1][(nf & 1) * 2 + 1]);
    };

    // epilogue lane constants
    const int g8   = lane >> 2;
    const int tig  = lane & 3;
    const bool odd = tig & 1;
    const int jsub = tig >> 1;

    // ---- prologue: fills 0,1,2 of the continuous ring ----
    do_fill(0); do_fill(1); do_fill(2);
    cp_wait<1>();
    __syncthreads();

    int g = 0;                                        // global consume counter
    ldsm_step(0, 0, 0);                               // (first tile, ks0) -> buf0

    for (int t = blockIdx.x; t < TOTAL_TILES; t += stride) {
        const int m0 = (t & (MTILES - 1)) * BM;
        const int n0 = (t >> 7) * BN;

#pragma unroll
        for (int mf = 0; mf < 2; mf++)
#pragma unroll
            for (int nf = 0; nf < 8; nf++)
#pragma unroll
                for (int r = 0; r < 4; r++) acc[mf][nf][r] = 0.0f;

        for (int kt = 0; kt < KITERS; kt++) {
            const int st = g & 3;
            do_fill((g + 3) & 3);                     // fill index g+3 (ring continues)

            ldsm_step(1, st, 16);                     // (g, ks1) -> buf1
            mma_step(0);                              // MMA (g, ks0)
            if (kt < KITERS - 1)
                ldsm_step(0, (g + 1) & 3, 0);         // (g+1, ks0) -> buf0 (stage visible)
            mma_step(1);                              // MMA (g, ks1)

            // done <= group g+2 -> after barrier, stages g+1 AND g+2 visible to all
            cp_wait<1>();
            __syncthreads();
            g++;
        }

        // ---------- fused LSTM epilogue (from accumulator registers) ----------
        // c-frag layout: d0,d1 -> (row=gr, cols 2*tig+{0,1}); d2,d3 -> (row=gr+8).
        // Gate-interleaved N: cols 4u..4u+3 = gates i,f,g,o of hidden unit.
        // Even tig holds (zi,zf); odd tig holds (zg,zo). Pair-exchange via shfl.xor(1).
#pragma unroll
        for (int mf = 0; mf < 2; mf++) {
            const int m = m0 + wm + mf * 16 + g8 + (odd ? 8 : 0);
            const float* crow = c_in + (size_t)m * kNH;
            float* ocrow = outC + (size_t)m * kNH;
            float* ohrow = outH + (size_t)m * kNH;
#pragma unroll
            for (int nf = 0; nf < 8; nf++) {
                float* d = acc[mf][nf];
                float v0 = __shfl_xor_sync(0xffffffffu, d[0], 1);
                float v1 = __shfl_xor_sync(0xffffffffu, d[1], 1);
                float v2 = __shfl_xor_sync(0xffffffffu, d[2], 1);
                float v3 = __shfl_xor_sync(0xffffffffu, d[3], 1);
                float zi = odd ? v2 : d[0];
                float zf = odd ? v3 : d[1];
                float zg = odd ? d[2] : v0;
                float zo = odd ? d[3] : v1;
                const int ncol = n0 + wn + nf * 8;    // global gemm column base
                const int j = (ncol >> 2) + jsub;     // hidden-unit index
                float4 bb = __ldg((const float4*)(g_bias + 4 * j));
                zi += bb.x; zf += bb.y; zg += bb.z; zo += bb.w;
                float it = sigf(zi), ft = sigf(zf), gt = tanha(zg), ot = sigf(zo);
                float cc = ft * __ldg(crow + j) + it * gt;
                ocrow[j] = cc;
                ohrow[j] = ot * tanha(cc);
            }
        }

        // first fragments of the NEXT tile (stage g visible from the last wait)
        if (t + stride < TOTAL_TILES)
            ldsm_step(0, g & 3, 0);
    }
}

// ================= host launch =================
extern "C" void kernel_launch(void* const* d_in, const int* in_sizes, int n_in,
                              void* d_out, int out_size)
{
    const float* x = (const float*)d_in[0];
    const float* c = (const float*)d_in[1];
    const float* h = (const float*)d_in[2];
    WPtrs wp;
    for (int g = 0; g < 4; g++) {
        wp.wx[g] = (const float*)d_in[3 + 2 * g];
        wp.bx[g] = (const float*)d_in[4 + 2 * g];
        wp.wh[g] = (const float*)d_in[11 + 2 * g];
        wp.bh[g] = (const float*)d_in[12 + 2 * g];
    }

    cudaFuncSetAttribute(lstm_gemm_kernel,
                         cudaFuncAttributeMaxDynamicSharedMemorySize, SMEM_DYN);

    int smCount = 148;
    cudaDeviceGetAttribute(&smCount, cudaDevAttrMultiProcessorCount, 0);
    const int numCtas = 2 * smCount;                  // 2 CTAs/SM persistent

    pack_A_kernel<<<(kM * (kK / 8)) / 256, 256>>>(x, h);
    pack_W_kernel<<<(kN * (kK / 8)) / 256, 256>>>(wp);
    pack_bias_kernel<<<kN / 256, 256>>>(wp);

    float* outC = (float*)d_out;
    float* outH = outC + (size_t)kM * kNH;
    lstm_gemm_kernel<<<numCtas, 256, SMEM_DYN>>>(c, outC, outH);
}

// round 16
// speedup vs baseline: 1.2349x; 1.0256x over previous
#include <cuda_runtime.h>
#include <cuda_fp16.h>
#include <cstdint>
#include <cstddef>

#define DEVI __device__ __forceinline__

// ---------------- problem sizes ----------------
static constexpr int kM   = 16384;   // 64*256 tokens
static constexpr int kNIn = 512;
static constexpr int kNH  = 1024;
static constexpr int kK   = 1536;    // 512 + 1024
static constexpr int kN   = 4096;    // 4 gates * 1024, gate-interleaved rows (4*j+g)

// ---------------- gemm tiling ----------------
static constexpr int BM = 128;
static constexpr int BN = 128;
static constexpr int BK = 32;                    // halves per k-tile (2 ks-steps of 16)
static constexpr int STAGES = 4;
static constexpr int KITERS = kK / BK;           // 48
static constexpr int ROW_B  = 80;                // padded row stride (64B data + 16B pad)
static constexpr int A_BYTES = BM * ROW_B;       // 10240
static constexpr int B_BYTES = BN * ROW_B;       // 10240
static constexpr int STAGE_B = A_BYTES + B_BYTES;            // 20480
static constexpr int SMEM_DYN = STAGES * STAGE_B;            // 81920 (x2 CTA = 160KB/SM)

// ---------------- scratch (device globals; no runtime alloc) ----------------
__device__ __align__(128) __half g_Apack[(size_t)kM * kK];   // 48 MB: [m, 0:512]=x, [m,512:1536]=h
__device__ __align__(128) __half g_Wpack[(size_t)kN * kK];   // 12 MB: row 4j+g
__device__ __align__(16)  float  g_bias[kN];                 // bx+bh, gate-interleaved

// ================= pack kernels =================
struct WPtrs {
    const float* wx[4];
    const float* wh[4];
    const float* bx[4];
    const float* bh[4];
};

DEVI uint4 cvt8(const float* src) {
    float4 a = *(const float4*)src;
    float4 b = *(const float4*)(src + 4);
    __half2 p0 = __floats2half2_rn(a.x, a.y);
    __half2 p1 = __floats2half2_rn(a.z, a.w);
    __half2 p2 = __floats2half2_rn(b.x, b.y);
    __half2 p3 = __floats2half2_rn(b.z, b.w);
    uint4 o;
    o.x = *(const unsigned*)&p0; o.y = *(const unsigned*)&p1;
    o.z = *(const unsigned*)&p2; o.w = *(const unsigned*)&p3;
    return o;
}

__global__ void pack_A_kernel(const float* __restrict__ x, const float* __restrict__ h) {
    unsigned g = blockIdx.x * blockDim.x + threadIdx.x;     // one group of 8 halves
    unsigned m  = g / (kK / 8);
    unsigned kk = (g % (kK / 8)) * 8;
    const float* src = (kk < (unsigned)kNIn) ? (x + (size_t)m * kNIn + kk)
                                             : (h + (size_t)m * kNH + (kk - kNIn));
    *(uint4*)(g_Apack + (size_t)g * 8) = cvt8(src);
}

__global__ void pack_W_kernel(WPtrs p) {
    unsigned g = blockIdx.x * blockDim.x + threadIdx.x;
    unsigned n  = g / (kK / 8);
    unsigned kk = (g % (kK / 8)) * 8;
    unsigned j = n >> 2, gate = n & 3;
    const float* src = (kk < (unsigned)kNIn) ? (p.wx[gate] + (size_t)j * kNIn + kk)
                                             : (p.wh[gate] + (size_t)j * kNH + (kk - kNIn));
    *(uint4*)(g_Wpack + (size_t)g * 8) = cvt8(src);
}

__global__ void pack_bias_kernel(WPtrs p) {
    unsigned n = blockIdx.x * blockDim.x + threadIdx.x;
    if (n < (unsigned)kN) {
        unsigned j = n >> 2, gate = n & 3;
        g_bias[n] = p.bx[gate][j] + p.bh[gate][j];
    }
}

// ================= ptx helpers (sm_100-base-target safe) =================
DEVI uint32_t smem_u32(const void* p) {
    uint32_t a;
    asm("{ .reg .u64 t; cvta.to.shared.u64 t, %1; cvt.u32.u64 %0, t; }" : "=r"(a) : "l"(p));
    return a;
}
DEVI void cp_async16(uint32_t saddr, const void* gaddr) {
    asm volatile("cp.async.cg.shared.global [%0], [%1], 16;" :: "r"(saddr), "l"(gaddr));
}
DEVI void cp_commit() { asm volatile("cp.async.commit_group;" ::: "memory"); }
template <int N> DEVI void cp_wait() { asm volatile("cp.async.wait_group %0;" :: "n"(N) : "memory"); }

DEVI void ldsm_x4(uint32_t& r0, uint32_t& r1, uint32_t& r2, uint32_t& r3, uint32_t addr) {
    asm volatile("ldmatrix.sync.aligned.m8n8.x4.shared.b16 {%0,%1,%2,%3}, [%4];"
                 : "=r"(r0), "=r"(r1), "=r"(r2), "=r"(r3) : "r"(addr));
}
DEVI void mma16816(float* d, const uint32_t* a, uint32_t b0, uint32_t b1) {
    asm volatile(
        "mma.sync.aligned.m16n8k16.row.col.f32.f16.f16.f32 "
        "{%0,%1,%2,%3}, {%4,%5,%6,%7}, {%8,%9}, {%0,%1,%2,%3};"
        : "+f"(d[0]), "+f"(d[1]), "+f"(d[2]), "+f"(d[3])
        : "r"(a[0]), "r"(a[1]), "r"(a[2]), "r"(a[3]), "r"(b0), "r"(b1));
}

DEVI float tanha(float x) { float y; asm("tanh.approx.f32 %0, %1;" : "=f"(y) : "f"(x)); return y; }
DEVI float sigf(float x)  { return fmaf(0.5f, tanha(0.5f * x), 0.5f); }

// ================= fused GEMM + LSTM epilogue =================
// CTA 128x128, 256 threads = 8 warps, warp grid 4(M) x 2(N); warp tile 32x64.
// 2 CTAs/SM. R12 cross-tile fragment pipelining (STAGES=4 + wait_group<1>).
// Grid is N-fastest (blockIdx.x = N tile): each wave shares few A tiles and
// streams all of B once -> DRAM re-reads drop ~670MB -> ~216MB.
__global__ void __launch_bounds__(256, 2) lstm_gemm_kernel(
    const float* __restrict__ c_in,
    float* __restrict__ outC,
    float* __restrict__ outH)
{
    extern __shared__ char smem[];
    const uint32_t sb = smem_u32(smem);

    const int tid  = threadIdx.x;
    const int lane = tid & 31;
    const int wid  = tid >> 5;
    const int wm   = (wid & 3) * 32;     // warp M offset in tile
    const int wn   = (wid >> 2) * 64;    // warp N offset in tile
    const int m0   = blockIdx.y * BM;    // N-fastest linearization
    const int n0   = blockIdx.x * BN;

    // --- cp.async stage loader: 4 x 16B per thread per stage ---
    auto load_stage = [&](int stage, int kt) {
        const uint32_t sA = sb + stage * STAGE_B;
        const uint32_t sB = sA + A_BYTES;
        const int kh = kt * BK;                       // k offset in halves
#pragma unroll
        for (int i = 0; i < 2; i++) {
            int id  = tid + i * 256;                  // 0..511
            int row = id >> 2;
            int seg = id & 3;
            cp_async16(sA + row * ROW_B + seg * 16,
                       g_Apack + (size_t)(m0 + row) * kK + kh + seg * 8);
            cp_async16(sB + row * ROW_B + seg * 16,
                       g_Wpack + (size_t)(n0 + row) * kK + kh + seg * 8);
        }
    };

    // prologue: load tiles 0,1,2 (3 groups)
#pragma unroll
    for (int s = 0; s < 3; s++) { load_stage(s, s); cp_commit(); }

    float acc[2][8][4];
#pragma unroll
    for (int mf = 0; mf < 2; mf++)
#pragma unroll
        for (int nf = 0; nf < 8; nf++)
#pragma unroll
            for (int r = 0; r < 4; r++) acc[mf][nf][r] = 0.0f;

    // per-lane ldmatrix address components
    const int a_row = wm + (lane & 15);               // + mf*16
    const int a_kof = (lane >> 4) << 3;               // + ks
    const int b_row = wn + (lane & 7) + ((lane >> 4) << 3);   // + nb*16
    const int b_kof = ((lane >> 3) & 1) << 3;         // + ks

    uint32_t ra[2][2][4], rb[2][4][4];                // [buf][frag][reg]

    auto ldsm_step = [&](int buf, int stage, int ks) {
        const uint32_t sA = sb + stage * STAGE_B;
        const uint32_t sB = sA + A_BYTES;
#pragma unroll
        for (int mf = 0; mf < 2; mf++)
            ldsm_x4(ra[buf][mf][0], ra[buf][mf][1], ra[buf][mf][2], ra[buf][mf][3],
                    sA + (a_row + mf * 16) * ROW_B + (ks + a_kof) * 2);
#pragma unroll
        for (int nb = 0; nb < 4; nb++)
            ldsm_x4(rb[buf][nb][0], rb[buf][nb][1], rb[buf][nb][2], rb[buf][nb][3],
                    sB + (b_row + nb * 16) * ROW_B + (ks + b_kof) * 2);
    };
    auto mma_step = [&](int buf) {
#pragma unroll
        for (int mf = 0; mf < 2; mf++)
#pragma unroll
            for (int nf = 0; nf < 8; nf++)
                mma16816(acc[mf][nf], ra[buf][mf],
                         rb[buf][nf >> 1][(nf & 1) * 2], rb[buf][nf >> 1][(nf & 1) * 2 + 1]);
    };

    // wait until groups <= 1 done (stages 0,1 visible after the barrier)
    cp_wait<1>();
    __syncthreads();
    ldsm_step(0, 0, 0);                               // (tile0, ks0) -> buf0

    for (int kt = 0; kt < KITERS; kt++) {
        const int st = kt & 3;
        // prefetch gmem for tile kt+3 into stage (kt+3)&3 == (kt-1)&3
        // (all warps are past tile kt-1: guaranteed by the barrier below of iter kt-1)
        if (kt + 3 < KITERS) { load_stage((kt + 3) & 3, kt + 3); cp_commit(); }

        ldsm_step(1, st, 16);                         // (kt, ks1) -> buf1
        mma_step(0);                                  // MMA (kt, ks0)
        ldsm_step(0, (kt + 1) & 3, 0);                // (kt+1, ks0) -> buf0 (stage kt+1 visible)
        mma_step(1);                                  // MMA (kt, ks1)

        // done <= group kt+2 -> after barrier, stages kt+1 AND kt+2 visible to all
        cp_wait<1>();
        __syncthreads();
    }

    // ---------- fused LSTM epilogue (from accumulator registers) ----------
    // c-frag layout: d0,d1 -> (row=g, cols 2*tig+{0,1}); d2,d3 -> (row=g+8).
    // Gate-interleaved N: cols 4u..4u+3 = gates i,f,g,o of hidden unit.
    // Even tig holds (zi,zf); odd tig holds (zg,zo). Pair-exchange via shfl.xor(1):
    //   even thread -> full quadruple for row g;  odd thread -> row g+8.
    const int g8   = lane >> 2;
    const int tig  = lane & 3;
    const bool odd = tig & 1;
    const int jsub = tig >> 1;                        // unit-within-nfrag

#pragma unroll
    for (int mf = 0; mf < 2; mf++) {
        const int m = m0 + wm + mf * 16 + g8 + (odd ? 8 : 0);
        const float* crow = c_in + (size_t)m * kNH;
        float* ocrow = outC + (size_t)m * kNH;
        float* ohrow = outH + (size_t)m * kNH;
#pragma unroll
        for (int nf = 0; nf < 8; nf++) {
            float* d = acc[mf][nf];
            float v0 = __shfl_xor_sync(0xffffffffu, d[0], 1);
            float v1 = __shfl_xor_sync(0xffffffffu, d[1], 1);
            float v2 = __shfl_xor_sync(0xffffffffu, d[2], 1);
            float v3 = __shfl_xor_sync(0xffffffffu, d[3], 1);
            float zi = odd ? v2 : d[0];
            float zf = odd ? v3 : d[1];
            float zg = odd ? d[2] : v0;
            float zo = odd ? d[3] : v1;
            const int ncol = n0 + wn + nf * 8;        // global gemm column base
            const int j = (ncol >> 2) + jsub;         // hidden-unit index
            float4 bb = __ldg((const float4*)(g_bias + 4 * j));
            zi += bb.x; zf += bb.y; zg += bb.z; zo += bb.w;
            float it = sigf(zi), ft = sigf(zf), gt = tanha(zg), ot = sigf(zo);
            float cc = ft * __ldg(crow + j) + it * gt;
            ocrow[j] = cc;
            ohrow[j] = ot * tanha(cc);
        }
    }
}

// ================= host launch =================
extern "C" void kernel_launch(void* const* d_in, const int* in_sizes, int n_in,
                              void* d_out, int out_size)
{
    const float* x = (const float*)d_in[0];
    const float* c = (const float*)d_in[1];
    const float* h = (const float*)d_in[2];
    WPtrs wp;
    for (int g = 0; g < 4; g++) {
        wp.wx[g] = (const float*)d_in[3 + 2 * g];
        wp.bx[g] = (const float*)d_in[4 + 2 * g];
        wp.wh[g] = (const float*)d_in[11 + 2 * g];
        wp.bh[g] = (const float*)d_in[12 + 2 * g];
    }

    cudaFuncSetAttribute(lstm_gemm_kernel,
                         cudaFuncAttributeMaxDynamicSharedMemorySize, SMEM_DYN);

    pack_A_kernel<<<(kM * (kK / 8)) / 256, 256>>>(x, h);
    pack_W_kernel<<<(kN * (kK / 8)) / 256, 256>>>(wp);
    pack_bias_kernel<<<kN / 256, 256>>>(wp);

    float* outC = (float*)d_out;
    float* outH = outC + (size_t)kM * kNH;
    // N-fastest grid: x = N tiles (32), y = M tiles (128)
    lstm_gemm_kernel<<<dim3(kN / BN, kM / BM), 256, SMEM_DYN>>>(c, outC, outH);
}